// round 4
// baseline (speedup 1.0000x reference)
#include <cuda_runtime.h>
#include <math.h>

#define NTOK 4096   // B*S
#define HDIM 2048
#define DDIM 2048
#define NEXP 8

// ---------------- scratch (device globals; no allocations allowed) ----------
__device__ int   g_count[NEXP];
__device__ int   g_list [NEXP * NTOK];   // token index per (expert, position)
__device__ float g_lgate[NEXP * NTOK];   // renormalized gate
__device__ int   g_lslot[NEXP * NTOK];   // output slot = token*2 + k (k=0 top1, k=1 top2)
__device__ float g_scratch[(size_t)2 * NTOK * DDIM];  // 64 MiB: per (token,k) expert outputs

// ---------------- f32x2 packed-FMA helpers (sm_103a FFMA2 path) -------------
__device__ __forceinline__ unsigned long long pk2(float lo, float hi) {
    unsigned long long r;
    asm("mov.b64 %0, {%1, %2};" : "=l"(r) : "f"(lo), "f"(hi));
    return r;
}
__device__ __forceinline__ void upk2(unsigned long long v, float& lo, float& hi) {
    asm("mov.b64 {%0, %1}, %2;" : "=f"(lo), "=f"(hi) : "l"(v));
}
__device__ __forceinline__ unsigned long long ffma2(unsigned long long a,
                                                    unsigned long long b,
                                                    unsigned long long c) {
    unsigned long long d;
    asm("fma.rn.f32x2 %0, %1, %2, %3;" : "=l"(d) : "l"(a), "l"(b), "l"(c));
    return d;
}

__device__ __forceinline__ float gelu_tanh(float v) {
    // JAX default gelu (approximate=True)
    const float c0 = 0.7978845608028654f;   // sqrt(2/pi)
    const float c1 = 0.044715f;
    float u = c0 * (v + c1 * v * v * v);
    return 0.5f * v * (1.0f + tanhf(u));
}

// ---------------- K0: zero the per-expert counters ---------------------------
__global__ void k_init() {
    if (threadIdx.x < NEXP) g_count[threadIdx.x] = 0;
}

// ---------------- K1: router (logits -> top2 -> renorm gates -> compaction) --
__global__ __launch_bounds__(256) void k_router(const float* __restrict__ x,
                                                const float* __restrict__ rw,
                                                const float* __restrict__ rb) {
    const int row = blockIdx.x;
    const int tid = threadIdx.x;

    float l[NEXP];
#pragma unroll
    for (int e = 0; e < NEXP; ++e) l[e] = 0.f;

    const float* xr = x + (size_t)row * HDIM;
    for (int h = tid; h < HDIM; h += 256) {
        float xv = xr[h];
        float4 w0 = *(const float4*)(rw + (size_t)h * NEXP);
        float4 w1 = *(const float4*)(rw + (size_t)h * NEXP + 4);
        l[0] += xv * w0.x; l[1] += xv * w0.y; l[2] += xv * w0.z; l[3] += xv * w0.w;
        l[4] += xv * w1.x; l[5] += xv * w1.y; l[6] += xv * w1.z; l[7] += xv * w1.w;
    }

    __shared__ float red[NEXP][256];
#pragma unroll
    for (int e = 0; e < NEXP; ++e) red[e][tid] = l[e];
    __syncthreads();
    for (int s = 128; s > 0; s >>= 1) {
        if (tid < s) {
#pragma unroll
            for (int e = 0; e < NEXP; ++e) red[e][tid] += red[e][tid + s];
        }
        __syncthreads();
    }

    if (tid == 0) {
        float lg[NEXP];
#pragma unroll
        for (int e = 0; e < NEXP; ++e) lg[e] = red[e][0] + rb[e];

        // top-2 by logit (softmax is monotone); ties -> lower index (matches top_k)
        int i0 = 0; float b0 = lg[0];
#pragma unroll
        for (int e = 1; e < NEXP; ++e) if (lg[e] > b0) { b0 = lg[e]; i0 = e; }
        int i1 = (i0 == 0) ? 1 : 0; float b1 = lg[i1];
#pragma unroll
        for (int e = 0; e < NEXP; ++e)
            if (e != i0 && lg[e] > b1) { b1 = lg[e]; i1 = e; }

        // renormalized 2-way softmax
        float ex = expf(b1 - b0);           // <= 1, stable
        float g0 = 1.0f / (1.0f + ex);
        float g1 = ex * g0;

        int p0 = atomicAdd(&g_count[i0], 1);
        g_list [i0 * NTOK + p0] = row;
        g_lgate[i0 * NTOK + p0] = g0;
        g_lslot[i0 * NTOK + p0] = row * 2 + 0;
        int p1 = atomicAdd(&g_count[i1], 1);
        g_list [i1 * NTOK + p1] = row;
        g_lgate[i1 * NTOK + p1] = g1;
        g_lslot[i1 * NTOK + p1] = row * 2 + 1;
    }
}

// ---------------- K2: grouped expert GEMM (gathered rows) --------------------
// grid = (DDIM/128, NTOK/128, NEXP), 256 threads, 128x128 tile, TK=8,
// 8x8 microtile as 8x4 f32x2 accumulators. Epilogue: gate * gelu(acc + b),
// scatter to g_scratch[slot].
__global__ __launch_bounds__(256, 2) void k_expert(const float* __restrict__ x,
                                                   const float* __restrict__ ew,
                                                   const float* __restrict__ eb) {
    const int e = blockIdx.z;
    const int n = g_count[e];
    const int mbase = blockIdx.y * 128;
    if (mbase >= n) return;
    const int dbase = blockIdx.x * 128;
    const float* __restrict__ W = ew + (size_t)e * HDIM * DDIM;

    const int tid  = threadIdx.x;
    const int arow = tid >> 1;            // 0..127
    const int aq   = (tid & 1) * 4;       // 0 or 4
    const int brow = tid >> 5;            // 0..7
    const int bc   = (tid & 31) * 4;      // 0..124

    const int lrowA = mbase + arow;
    // invalid rows fall back to a known-valid list entry (mbase < n)
    const int tok = (lrowA < n) ? g_list[e * NTOK + lrowA] : g_list[e * NTOK + mbase];
    const float* Aptr = x + (size_t)tok * HDIM + aq;
    const float* Bptr = W + (size_t)brow * DDIM + dbase + bc;

    __shared__ float As[2][8][128];   // k-major (transposed on store)
    __shared__ float Bs[2][8][128];

    const int tx = tid & 15, ty = tid >> 4;
    const int r0 = ty * 8, c0 = tx * 8;

    unsigned long long acc[8][4];
#pragma unroll
    for (int i = 0; i < 8; ++i)
#pragma unroll
        for (int j = 0; j < 4; ++j) acc[i][j] = 0ull;

    {   // prologue: chunk 0
        float4 av = *(const float4*)Aptr;
        float4 bv = *(const float4*)Bptr;
        As[0][aq + 0][arow] = av.x; As[0][aq + 1][arow] = av.y;
        As[0][aq + 2][arow] = av.z; As[0][aq + 3][arow] = av.w;
        *(float4*)&Bs[0][brow][bc] = bv;
    }
    __syncthreads();

    const int NC = HDIM / 8;
    for (int kc = 0; kc < NC; ++kc) {
        const int cur = kc & 1;
        float4 nav, nbv;
        const bool more = (kc + 1 < NC);
        if (more) {
            nav = *(const float4*)(Aptr + (size_t)(kc + 1) * 8);
            nbv = *(const float4*)(Bptr + (size_t)(kc + 1) * 8 * DDIM);
        }
#pragma unroll
        for (int kk = 0; kk < 8; ++kk) {
            float4 a0 = *(const float4*)&As[cur][kk][r0];
            float4 a1 = *(const float4*)&As[cur][kk][r0 + 4];
            float4 b0 = *(const float4*)&Bs[cur][kk][c0];
            float4 b1 = *(const float4*)&Bs[cur][kk][c0 + 4];
            unsigned long long B01 = pk2(b0.x, b0.y), B23 = pk2(b0.z, b0.w);
            unsigned long long B45 = pk2(b1.x, b1.y), B67 = pk2(b1.z, b1.w);
            float aa[8] = {a0.x, a0.y, a0.z, a0.w, a1.x, a1.y, a1.z, a1.w};
#pragma unroll
            for (int i = 0; i < 8; ++i) {
                unsigned long long ad = pk2(aa[i], aa[i]);
                acc[i][0] = ffma2(ad, B01, acc[i][0]);
                acc[i][1] = ffma2(ad, B23, acc[i][1]);
                acc[i][2] = ffma2(ad, B45, acc[i][2]);
                acc[i][3] = ffma2(ad, B67, acc[i][3]);
            }
        }
        if (more) {
            const int nxt = cur ^ 1;
            As[nxt][aq + 0][arow] = nav.x; As[nxt][aq + 1][arow] = nav.y;
            As[nxt][aq + 2][arow] = nav.z; As[nxt][aq + 3][arow] = nav.w;
            *(float4*)&Bs[nxt][brow][bc] = nbv;
        }
        __syncthreads();
    }

    // epilogue: gate * gelu(acc + bias) -> scratch[slot]
#pragma unroll
    for (int i = 0; i < 8; ++i) {
        int lr = mbase + r0 + i;
        if (lr < n) {
            int   slot = g_lslot[e * NTOK + lr];
            float gate = g_lgate[e * NTOK + lr];
            float* op = g_scratch + (size_t)slot * DDIM + dbase + c0;
            const float* bb = eb + (size_t)e * DDIM + dbase + c0;
            float v[8];
#pragma unroll
            for (int j = 0; j < 4; ++j) upk2(acc[i][j], v[2 * j], v[2 * j + 1]);
            float4 o0, o1;
            o0.x = gate * gelu_tanh(v[0] + bb[0]);
            o0.y = gate * gelu_tanh(v[1] + bb[1]);
            o0.z = gate * gelu_tanh(v[2] + bb[2]);
            o0.w = gate * gelu_tanh(v[3] + bb[3]);
            o1.x = gate * gelu_tanh(v[4] + bb[4]);
            o1.y = gate * gelu_tanh(v[5] + bb[5]);
            o1.z = gate * gelu_tanh(v[6] + bb[6]);
            o1.w = gate * gelu_tanh(v[7] + bb[7]);
            *(float4*)op       = o0;
            *(float4*)(op + 4) = o1;
        }
    }
}

// ---------------- K3: output projection (combine fused into A-load) ----------
// combined[t] = scratch[2t] + scratch[2t+1]; out = combined @ out_w + out_b
__global__ __launch_bounds__(256, 2) void k_outproj(const float* __restrict__ ow,
                                                    const float* __restrict__ ob,
                                                    float* __restrict__ out) {
    const int mbase = blockIdx.y * 128;
    const int dbase = blockIdx.x * 128;

    const int tid  = threadIdx.x;
    const int arow = tid >> 1;
    const int aq   = (tid & 1) * 4;
    const int brow = tid >> 5;
    const int bc   = (tid & 31) * 4;

    const int m = mbase + arow;   // always < NTOK (4096/128 exact)
    const float* A0 = g_scratch + (size_t)(2 * m) * DDIM + aq;
    const float* A1 = A0 + DDIM;
    const float* Bptr = ow + (size_t)brow * DDIM + dbase + bc;

    __shared__ float As[2][8][128];
    __shared__ float Bs[2][8][128];

    const int tx = tid & 15, ty = tid >> 4;
    const int r0 = ty * 8, c0 = tx * 8;

    unsigned long long acc[8][4];
#pragma unroll
    for (int i = 0; i < 8; ++i)
#pragma unroll
        for (int j = 0; j < 4; ++j) acc[i][j] = 0ull;

    {
        float4 u = *(const float4*)A0;
        float4 w = *(const float4*)A1;
        float4 bv = *(const float4*)Bptr;
        As[0][aq + 0][arow] = u.x + w.x; As[0][aq + 1][arow] = u.y + w.y;
        As[0][aq + 2][arow] = u.z + w.z; As[0][aq + 3][arow] = u.w + w.w;
        *(float4*)&Bs[0][brow][bc] = bv;
    }
    __syncthreads();

    const int NC = DDIM / 8;
    for (int kc = 0; kc < NC; ++kc) {
        const int cur = kc & 1;
        float4 nu, nw, nbv;
        const bool more = (kc + 1 < NC);
        if (more) {
            nu  = *(const float4*)(A0 + (size_t)(kc + 1) * 8);
            nw  = *(const float4*)(A1 + (size_t)(kc + 1) * 8);
            nbv = *(const float4*)(Bptr + (size_t)(kc + 1) * 8 * DDIM);
        }
#pragma unroll
        for (int kk = 0; kk < 8; ++kk) {
            float4 a0 = *(const float4*)&As[cur][kk][r0];
            float4 a1 = *(const float4*)&As[cur][kk][r0 + 4];
            float4 b0 = *(const float4*)&Bs[cur][kk][c0];
            float4 b1 = *(const float4*)&Bs[cur][kk][c0 + 4];
            unsigned long long B01 = pk2(b0.x, b0.y), B23 = pk2(b0.z, b0.w);
            unsigned long long B45 = pk2(b1.x, b1.y), B67 = pk2(b1.z, b1.w);
            float aa[8] = {a0.x, a0.y, a0.z, a0.w, a1.x, a1.y, a1.z, a1.w};
#pragma unroll
            for (int i = 0; i < 8; ++i) {
                unsigned long long ad = pk2(aa[i], aa[i]);
                acc[i][0] = ffma2(ad, B01, acc[i][0]);
                acc[i][1] = ffma2(ad, B23, acc[i][1]);
                acc[i][2] = ffma2(ad, B45, acc[i][2]);
                acc[i][3] = ffma2(ad, B67, acc[i][3]);
            }
        }
        if (more) {
            const int nxt = cur ^ 1;
            As[nxt][aq + 0][arow] = nu.x + nw.x; As[nxt][aq + 1][arow] = nu.y + nw.y;
            As[nxt][aq + 2][arow] = nu.z + nw.z; As[nxt][aq + 3][arow] = nu.w + nw.w;
            *(float4*)&Bs[nxt][brow][bc] = nbv;
        }
        __syncthreads();
    }

#pragma unroll
    for (int i = 0; i < 8; ++i) {
        int row = mbase + r0 + i;
        float* op = out + (size_t)row * DDIM + dbase + c0;
        const float* bb = ob + dbase + c0;
        float v[8];
#pragma unroll
        for (int j = 0; j < 4; ++j) upk2(acc[i][j], v[2 * j], v[2 * j + 1]);
        float4 o0, o1;
        o0.x = v[0] + bb[0]; o0.y = v[1] + bb[1];
        o0.z = v[2] + bb[2]; o0.w = v[3] + bb[3];
        o1.x = v[4] + bb[4]; o1.y = v[5] + bb[5];
        o1.z = v[6] + bb[6]; o1.w = v[7] + bb[7];
        *(float4*)op       = o0;
        *(float4*)(op + 4) = o1;
    }
}

// ---------------- launch ------------------------------------------------------
extern "C" void kernel_launch(void* const* d_in, const int* in_sizes, int n_in,
                              void* d_out, int out_size) {
    const float* x  = (const float*)d_in[0];   // [B,S,H]
    const float* rw = (const float*)d_in[1];   // [H,E]
    const float* rb = (const float*)d_in[2];   // [E]
    const float* ew = (const float*)d_in[3];   // [E,H,D]
    const float* eb = (const float*)d_in[4];   // [E,D]
    const float* ow = (const float*)d_in[5];   // [D,D]
    const float* ob = (const float*)d_in[6];   // [D]
    float* out = (float*)d_out;                // [B,S,D]

    k_init<<<1, 32>>>();
    k_router<<<NTOK, 256>>>(x, rw, rb);

    dim3 ge(DDIM / 128, NTOK / 128, NEXP);
    k_expert<<<ge, 256>>>(x, ew, eb);

    dim3 go(DDIM / 128, NTOK / 128);
    k_outproj<<<go, 256>>>(ow, ob, out);
}

// round 6
// speedup vs baseline: 1.6572x; 1.6572x over previous
#include <cuda_runtime.h>
#include <cuda_bf16.h>
#include <math.h>
#include <stdint.h>

#define NTOK 4096   // B*S
#define HDIM 2048
#define DDIM 2048
#define NEXP 8
#define BK   32                 // bf16 K elements per stage
#define NST  (HDIM / BK)        // 64 stages (HDIM == DDIM)

// padded smem rows: 32 bf16 data + 8 pad = 40 bf16 = 80 B  -> conflict-free frags
#define ROWB 80
#define TEN_BYTES (128 * ROWB)          // 10240 B per tensor tile
#define STAGE_BYTES (4 * TEN_BYTES)     // Ahi|Alo|Bhi|Blo
#define SMEM_HDR 1536
#define SMEM_GEMM (SMEM_HDR + 2 * STAGE_BYTES)   // 83456 B

// ---------------- scratch (device globals; no allocations allowed) ----------
__device__ int   g_count[NEXP];
__device__ int   g_list [NEXP * NTOK];
__device__ float g_lgate[NEXP * NTOK];
__device__ int   g_lslot[NEXP * NTOK];
__device__ float g_scratch[(size_t)2 * NTOK * DDIM];                        // 64 MiB
__device__ __align__(16) __nv_bfloat16 g_xhi [(size_t)NTOK * HDIM];
__device__ __align__(16) __nv_bfloat16 g_xlo [(size_t)NTOK * HDIM];
__device__ __align__(16) __nv_bfloat16 g_ewhi[(size_t)NEXP * DDIM * HDIM];  // [e][d][h]
__device__ __align__(16) __nv_bfloat16 g_ewlo[(size_t)NEXP * DDIM * HDIM];
__device__ __align__(16) __nv_bfloat16 g_owhi[(size_t)DDIM * DDIM];         // [f][d]
__device__ __align__(16) __nv_bfloat16 g_owlo[(size_t)DDIM * DDIM];
__device__ __align__(16) __nv_bfloat16 g_chi [(size_t)NTOK * DDIM];
__device__ __align__(16) __nv_bfloat16 g_clo [(size_t)NTOK * DDIM];

// ---------------- helpers ----------------------------------------------------
__device__ __forceinline__ void mma16816(float* c, const uint32_t* a, const uint32_t* b) {
    asm volatile(
        "mma.sync.aligned.m16n8k16.row.col.f32.bf16.bf16.f32 "
        "{%0,%1,%2,%3}, {%4,%5,%6,%7}, {%8,%9}, {%0,%1,%2,%3};"
        : "+f"(c[0]), "+f"(c[1]), "+f"(c[2]), "+f"(c[3])
        : "r"(a[0]), "r"(a[1]), "r"(a[2]), "r"(a[3]), "r"(b[0]), "r"(b[1]));
}
__device__ __forceinline__ unsigned pkbf2(float a, float b) {
    __nv_bfloat162 t = __floats2bfloat162_rn(a, b);
    return *reinterpret_cast<unsigned*>(&t);
}
__device__ __forceinline__ float gelu_tanh(float v) {
    const float c0 = 0.7978845608028654f, c1 = 0.044715f;
    float u = c0 * (v + c1 * v * v * v);
    return 0.5f * v * (1.0f + tanhf(u));
}

// ---------------- K0 + router -------------------------------------------------
__global__ void k_init() { if (threadIdx.x < NEXP) g_count[threadIdx.x] = 0; }

__global__ __launch_bounds__(256) void k_router(const float* __restrict__ x,
                                                const float* __restrict__ rw,
                                                const float* __restrict__ rb) {
    const int row = blockIdx.x, tid = threadIdx.x;
    float l[NEXP];
#pragma unroll
    for (int e = 0; e < NEXP; ++e) l[e] = 0.f;
    const float* xr = x + (size_t)row * HDIM;
    for (int h = tid; h < HDIM; h += 256) {
        float xv = xr[h];
        float4 w0 = *(const float4*)(rw + (size_t)h * NEXP);
        float4 w1 = *(const float4*)(rw + (size_t)h * NEXP + 4);
        l[0] += xv * w0.x; l[1] += xv * w0.y; l[2] += xv * w0.z; l[3] += xv * w0.w;
        l[4] += xv * w1.x; l[5] += xv * w1.y; l[6] += xv * w1.z; l[7] += xv * w1.w;
    }
    __shared__ float red[NEXP][256];
#pragma unroll
    for (int e = 0; e < NEXP; ++e) red[e][tid] = l[e];
    __syncthreads();
    for (int s = 128; s > 0; s >>= 1) {
        if (tid < s) {
#pragma unroll
            for (int e = 0; e < NEXP; ++e) red[e][tid] += red[e][tid + s];
        }
        __syncthreads();
    }
    if (tid == 0) {
        float lg[NEXP];
#pragma unroll
        for (int e = 0; e < NEXP; ++e) lg[e] = red[e][0] + rb[e];
        int i0 = 0; float b0 = lg[0];
#pragma unroll
        for (int e = 1; e < NEXP; ++e) if (lg[e] > b0) { b0 = lg[e]; i0 = e; }
        int i1 = (i0 == 0) ? 1 : 0; float b1 = lg[i1];
#pragma unroll
        for (int e = 0; e < NEXP; ++e) if (e != i0 && lg[e] > b1) { b1 = lg[e]; i1 = e; }
        float ex = expf(b1 - b0);
        float g0 = 1.0f / (1.0f + ex);
        float g1 = ex * g0;
        int p0 = atomicAdd(&g_count[i0], 1);
        g_list[i0 * NTOK + p0] = row; g_lgate[i0 * NTOK + p0] = g0; g_lslot[i0 * NTOK + p0] = row * 2;
        int p1 = atomicAdd(&g_count[i1], 1);
        g_list[i1 * NTOK + p1] = row; g_lgate[i1 * NTOK + p1] = g1; g_lslot[i1 * NTOK + p1] = row * 2 + 1;
    }
}

// ---------------- prep: fp32 -> split bf16 ------------------------------------
__global__ __launch_bounds__(256) void k_cvt_x(const float* __restrict__ x) {
    size_t j = ((size_t)blockIdx.x * 256 + threadIdx.x) << 2;
    float4 v = *(const float4*)(x + j);
    float hx = __bfloat162float(__float2bfloat16(v.x));
    float hy = __bfloat162float(__float2bfloat16(v.y));
    float hz = __bfloat162float(__float2bfloat16(v.z));
    float hw = __bfloat162float(__float2bfloat16(v.w));
    uint2 ph = { pkbf2(hx, hy), pkbf2(hz, hw) };
    uint2 pl = { pkbf2(v.x - hx, v.y - hy), pkbf2(v.z - hz, v.w - hw) };
    *(uint2*)(g_xhi + j) = ph;
    *(uint2*)(g_xlo + j) = pl;
}

__global__ __launch_bounds__(256) void k_cvt_ew(const float* __restrict__ ew) {
    __shared__ float t[32][33];
    const int e = blockIdx.z;
    const int d0 = blockIdx.x * 32, h0 = blockIdx.y * 32;
    const int tx = threadIdx.x, ty = threadIdx.y;
    const float* src = ew + (size_t)e * HDIM * DDIM;
    for (int j = ty; j < 32; j += 8)
        t[j][tx] = src[(size_t)(h0 + j) * DDIM + d0 + tx];
    __syncthreads();
    __nv_bfloat16* dh = g_ewhi + (size_t)e * DDIM * HDIM;
    __nv_bfloat16* dl = g_ewlo + (size_t)e * DDIM * HDIM;
    for (int j = ty; j < 32; j += 8) {
        float v = t[tx][j];
        float h = __bfloat162float(__float2bfloat16(v));
        size_t o = (size_t)(d0 + j) * HDIM + h0 + tx;
        dh[o] = __float2bfloat16(v);
        dl[o] = __float2bfloat16(v - h);
    }
}

__global__ __launch_bounds__(256) void k_cvt_ow(const float* __restrict__ ow) {
    __shared__ float t[32][33];
    const int f0 = blockIdx.x * 32, d0 = blockIdx.y * 32;
    const int tx = threadIdx.x, ty = threadIdx.y;
    for (int j = ty; j < 32; j += 8)
        t[j][tx] = ow[(size_t)(d0 + j) * DDIM + f0 + tx];
    __syncthreads();
    for (int j = ty; j < 32; j += 8) {
        float v = t[tx][j];
        float h = __bfloat162float(__float2bfloat16(v));
        size_t o = (size_t)(f0 + j) * DDIM + d0 + tx;
        g_owhi[o] = __float2bfloat16(v);
        g_owlo[o] = __float2bfloat16(v - h);
    }
}

__global__ __launch_bounds__(256) void k_combine() {
    size_t j = ((size_t)blockIdx.x * 256 + threadIdx.x) << 2;
    size_t t = j >> 11, d = j & 2047;
    const float* s = g_scratch + (t << 12) + d;
    float4 a = *(const float4*)s;
    float4 b = *(const float4*)(s + DDIM);
    float cx = a.x + b.x, cy = a.y + b.y, cz = a.z + b.z, cw = a.w + b.w;
    float hx = __bfloat162float(__float2bfloat16(cx));
    float hy = __bfloat162float(__float2bfloat16(cy));
    float hz = __bfloat162float(__float2bfloat16(cz));
    float hw = __bfloat162float(__float2bfloat16(cw));
    uint2 ph = { pkbf2(hx, hy), pkbf2(hz, hw) };
    uint2 pl = { pkbf2(cx - hx, cy - hy), pkbf2(cz - hz, cw - hw) };
    *(uint2*)(g_chi + j) = ph;
    *(uint2*)(g_clo + j) = pl;
}

// ---------------- core GEMM macro body ----------------------------------------
// 128x128 CTA tile, 256 thr = 8 warps (2x4), warp tile 64x32, BK=32 stages.
// 3-pass split-bf16: acc += Ahi*Bhi + Ahi*Blo + Alo*Bhi (fp32 accum in regs).

struct Frag { uint32_t a[4]; };

__device__ __forceinline__ void gemm_mainloop(
    char* smem, int tid,
    // per-stage gmem row sources
    const __nv_bfloat16* Ahi, const __nv_bfloat16* Alo, size_t aStride, const int* arow, // arow!=nullptr: gathered
    const __nv_bfloat16* Bhi, const __nv_bfloat16* Blo, size_t bRow0,                     // B rows bRow0+row
    float acc[4][4][4])
{
    const int lane = tid & 31, wid = tid >> 5;
    const int wm = (wid >> 2) * 64, wn = (wid & 3) * 32;
    const int g = lane >> 2, t = lane & 3;

    // loader: 4 tensors x 512 uint4 ; thread handles idx = tid + i*256
    auto load_stage = [&](int kc, int bsel) {
        char* base = smem + SMEM_HDR + bsel * STAGE_BYTES;
        const int kb = kc * BK;
#pragma unroll
        for (int i = 0; i < 2; ++i) {
            int idx = tid + (i << 8);
            int row = idx >> 2, seg = idx & 3;
            uint32_t so = (uint32_t)(row * ROWB + seg * 16);
            size_t ar = arow ? (size_t)arow[row] : (size_t)row;
            size_t aoff = ar * aStride + kb + seg * 8;
            *(uint4*)(base + so)                 = *(const uint4*)(Ahi + aoff);
            *(uint4*)(base + TEN_BYTES + so)     = *(const uint4*)(Alo + aoff);
            size_t boff = (bRow0 + row) * aStride + kb + seg * 8;
            *(uint4*)(base + 2 * TEN_BYTES + so) = *(const uint4*)(Bhi + boff);
            *(uint4*)(base + 3 * TEN_BYTES + so) = *(const uint4*)(Blo + boff);
        }
    };

    load_stage(0, 0);
    __syncthreads();

    for (int kc = 0; kc < NST; ++kc) {
        const int cur = kc & 1;
        if (kc + 1 < NST) load_stage(kc + 1, cur ^ 1);

        char* st = smem + SMEM_HDR + cur * STAGE_BYTES;
        char* pAh = st + (wm + g) * ROWB + t * 4;
        char* pAl = pAh + TEN_BYTES;
        char* pBh = st + 2 * TEN_BYTES + (wn + g) * ROWB + t * 4;
        char* pBl = pBh + TEN_BYTES;

#pragma unroll
        for (int ks = 0; ks < 2; ++ks) {
            const int ko = ks * 32;   // 16 bf16 = 32 bytes
            Frag Ah[4], Al[4];
            uint32_t Bh[4][2], Bl[4][2];
#pragma unroll
            for (int mt = 0; mt < 4; ++mt) {
                char* p = pAh + mt * (16 * ROWB) + ko;
                Ah[mt].a[0] = *(const uint32_t*)(p);
                Ah[mt].a[1] = *(const uint32_t*)(p + 8 * ROWB);
                Ah[mt].a[2] = *(const uint32_t*)(p + 16);
                Ah[mt].a[3] = *(const uint32_t*)(p + 8 * ROWB + 16);
            }
#pragma unroll
            for (int nt = 0; nt < 4; ++nt) {
                char* p = pBh + nt * (8 * ROWB) + ko;
                Bh[nt][0] = *(const uint32_t*)(p);
                Bh[nt][1] = *(const uint32_t*)(p + 16);
            }
#pragma unroll
            for (int mt = 0; mt < 4; ++mt)
#pragma unroll
                for (int nt = 0; nt < 4; ++nt)
                    mma16816(acc[mt][nt], Ah[mt].a, Bh[nt]);
#pragma unroll
            for (int nt = 0; nt < 4; ++nt) {
                char* p = pBl + nt * (8 * ROWB) + ko;
                Bl[nt][0] = *(const uint32_t*)(p);
                Bl[nt][1] = *(const uint32_t*)(p + 16);
            }
#pragma unroll
            for (int mt = 0; mt < 4; ++mt)
#pragma unroll
                for (int nt = 0; nt < 4; ++nt)
                    mma16816(acc[mt][nt], Ah[mt].a, Bl[nt]);
#pragma unroll
            for (int mt = 0; mt < 4; ++mt) {
                char* p = pAl + mt * (16 * ROWB) + ko;
                Al[mt].a[0] = *(const uint32_t*)(p);
                Al[mt].a[1] = *(const uint32_t*)(p + 8 * ROWB);
                Al[mt].a[2] = *(const uint32_t*)(p + 16);
                Al[mt].a[3] = *(const uint32_t*)(p + 8 * ROWB + 16);
            }
#pragma unroll
            for (int mt = 0; mt < 4; ++mt)
#pragma unroll
                for (int nt = 0; nt < 4; ++nt)
                    mma16816(acc[mt][nt], Al[mt].a, Bh[nt]);
        }
        __syncthreads();
    }
}

// ---------------- K2: expert GEMM ---------------------------------------------
__global__ __launch_bounds__(256, 1) void k_expert_mma(const float* __restrict__ eb) {
    extern __shared__ char smem[];
    const int e = blockIdx.z;
    const int n = g_count[e];
    const int mbase = blockIdx.y * 128;
    if (mbase >= n) return;
    const int dbase = blockIdx.x * 128;
    const int tid = threadIdx.x, lane = tid & 31, wid = tid >> 5;

    int*   s_tok  = (int*)  (smem);
    float* s_gate = (float*)(smem + 512);
    int*   s_slot = (int*)  (smem + 1024);
    if (tid < 128) {
        int lr = mbase + tid;
        int safe = (lr < n) ? lr : mbase;
        s_tok [tid] = g_list [e * NTOK + safe];
        s_gate[tid] = g_lgate[e * NTOK + safe];
        s_slot[tid] = g_lslot[e * NTOK + safe];
    }
    __syncthreads();

    float acc[4][4][4];
#pragma unroll
    for (int mt = 0; mt < 4; ++mt)
#pragma unroll
        for (int nt = 0; nt < 4; ++nt)
#pragma unroll
            for (int i = 0; i < 4; ++i) acc[mt][nt][i] = 0.f;

    const size_t eoff = (size_t)e * DDIM * HDIM;
    gemm_mainloop(smem, tid,
                  g_xhi, g_xlo, HDIM, s_tok,
                  g_ewhi + eoff, g_ewlo + eoff, (size_t)dbase,
                  acc);

    // epilogue: gate * gelu(acc + bias) -> scratch[slot]
    const int wm = (wid >> 2) * 64, wn = (wid & 3) * 32;
    const int g = lane >> 2, t = lane & 3;
#pragma unroll
    for (int mt = 0; mt < 4; ++mt) {
#pragma unroll
        for (int half = 0; half < 2; ++half) {
            int rloc = wm + mt * 16 + g + half * 8;
            if (mbase + rloc < n) {
                float gate = s_gate[rloc];
                int   slot = s_slot[rloc];
                float* orow = g_scratch + (size_t)slot * DDIM + dbase;
                const float* brow = eb + (size_t)e * DDIM + dbase;
#pragma unroll
                for (int nt = 0; nt < 4; ++nt) {
                    int col = wn + nt * 8 + t * 2;
                    float v0 = acc[mt][nt][half * 2 + 0] + brow[col];
                    float v1 = acc[mt][nt][half * 2 + 1] + brow[col + 1];
                    float2 o = { gate * gelu_tanh(v0), gate * gelu_tanh(v1) };
                    *(float2*)(orow + col) = o;
                }
            }
        }
    }
}

// ---------------- K3: output projection ---------------------------------------
__global__ __launch_bounds__(256, 1) void k_outproj_mma(const float* __restrict__ ob,
                                                        float* __restrict__ out) {
    extern __shared__ char smem[];
    const int mbase = blockIdx.y * 128;
    const int dbase = blockIdx.x * 128;
    const int tid = threadIdx.x, lane = tid & 31, wid = tid >> 5;

    float acc[4][4][4];
#pragma unroll
    for (int mt = 0; mt < 4; ++mt)
#pragma unroll
        for (int nt = 0; nt < 4; ++nt)
#pragma unroll
            for (int i = 0; i < 4; ++i) acc[mt][nt][i] = 0.f;

    gemm_mainloop(smem, tid,
                  g_chi + (size_t)mbase * DDIM, g_clo + (size_t)mbase * DDIM, DDIM, nullptr,
                  g_owhi, g_owlo, (size_t)dbase,
                  acc);

    const int wm = (wid >> 2) * 64, wn = (wid & 3) * 32;
    const int g = lane >> 2, t = lane & 3;
#pragma unroll
    for (int mt = 0; mt < 4; ++mt) {
#pragma unroll
        for (int half = 0; half < 2; ++half) {
            int row = mbase + wm + mt * 16 + g + half * 8;
            float* orow = out + (size_t)row * DDIM + dbase;
            const float* brow = ob + dbase;
#pragma unroll
            for (int nt = 0; nt < 4; ++nt) {
                int col = wn + nt * 8 + t * 2;
                float2 o = { acc[mt][nt][half * 2 + 0] + brow[col],
                             acc[mt][nt][half * 2 + 1] + brow[col + 1] };
                *(float2*)(orow + col) = o;
            }
        }
    }
}

// ---------------- launch --------------------------------------------------------
extern "C" void kernel_launch(void* const* d_in, const int* in_sizes, int n_in,
                              void* d_out, int out_size) {
    const float* x  = (const float*)d_in[0];
    const float* rw = (const float*)d_in[1];
    const float* rb = (const float*)d_in[2];
    const float* ew = (const float*)d_in[3];
    const float* eb = (const float*)d_in[4];
    const float* ow = (const float*)d_in[5];
    const float* ob = (const float*)d_in[6];
    float* out = (float*)d_out;

    cudaFuncSetAttribute(k_expert_mma,  cudaFuncAttributeMaxDynamicSharedMemorySize, SMEM_GEMM);
    cudaFuncSetAttribute(k_outproj_mma, cudaFuncAttributeMaxDynamicSharedMemorySize, SMEM_GEMM);

    k_init<<<1, 32>>>();
    k_router<<<NTOK, 256>>>(x, rw, rb);
    k_cvt_x<<<(NTOK * HDIM / 4) / 256, 256>>>(x);
    k_cvt_ew<<<dim3(DDIM / 32, HDIM / 32, NEXP), dim3(32, 8)>>>(ew);
    k_cvt_ow<<<dim3(DDIM / 32, DDIM / 32), dim3(32, 8)>>>(ow);

    dim3 ge(DDIM / 128, NTOK / 128, NEXP);
    k_expert_mma<<<ge, 256, SMEM_GEMM>>>(eb);

    k_combine<<<(NTOK * DDIM / 4) / 256, 256>>>();

    dim3 go(DDIM / 128, NTOK / 128);
    k_outproj_mma<<<go, 256, SMEM_GEMM>>>(ob, out);
}

// round 11
// speedup vs baseline: 2.1615x; 1.3043x over previous
#include <cuda_runtime.h>
#include <cuda_bf16.h>
#include <math.h>
#include <stdint.h>

#define NTOK 4096   // B*S
#define HDIM 2048
#define DDIM 2048
#define NEXP 8
#define BK   32                 // bf16 K elements per stage
#define NST  (HDIM / BK)        // 64 stages (HDIM == DDIM)

// padded smem rows: 32 bf16 data + 8 pad = 40 bf16 = 80 B -> conflict-free frags
#define ROWB 80
#define TEN_BYTES (128 * ROWB)          // 10240 B per tensor tile
#define STAGE_BYTES (4 * TEN_BYTES)     // Ahi|Alo|Bhi|Blo
#define SMEM_HDR 1536
#define SMEM_GEMM (SMEM_HDR + 2 * STAGE_BYTES)   // 83456 B

// ---------------- scratch (device globals; no allocations allowed) ----------
__device__ int   g_count[NEXP];
__device__ int   g_list [NEXP * NTOK];
__device__ float g_lgate[NEXP * NTOK];
__device__ int   g_lslot[NEXP * NTOK];
__device__ float g_scratch[(size_t)2 * NTOK * DDIM];                        // 64 MiB
__device__ __align__(16) __nv_bfloat16 g_xhi [(size_t)NTOK * HDIM];
__device__ __align__(16) __nv_bfloat16 g_xlo [(size_t)NTOK * HDIM];
__device__ __align__(16) __nv_bfloat16 g_ewhi[(size_t)NEXP * DDIM * HDIM];  // [e][d][h]
__device__ __align__(16) __nv_bfloat16 g_ewlo[(size_t)NEXP * DDIM * HDIM];
__device__ __align__(16) __nv_bfloat16 g_owhi[(size_t)DDIM * DDIM];         // [f][d]
__device__ __align__(16) __nv_bfloat16 g_owlo[(size_t)DDIM * DDIM];
__device__ __align__(16) __nv_bfloat16 g_chi [(size_t)NTOK * DDIM];
__device__ __align__(16) __nv_bfloat16 g_clo [(size_t)NTOK * DDIM];

// ---------------- helpers ----------------------------------------------------
__device__ __forceinline__ void mma16816(float* c, const uint32_t* a, const uint32_t* b) {
    asm volatile(
        "mma.sync.aligned.m16n8k16.row.col.f32.bf16.bf16.f32 "
        "{%0,%1,%2,%3}, {%4,%5,%6,%7}, {%8,%9}, {%0,%1,%2,%3};"
        : "+f"(c[0]), "+f"(c[1]), "+f"(c[2]), "+f"(c[3])
        : "r"(a[0]), "r"(a[1]), "r"(a[2]), "r"(a[3]), "r"(b[0]), "r"(b[1]));
}
__device__ __forceinline__ unsigned pkbf2(float a, float b) {
    __nv_bfloat162 t = __floats2bfloat162_rn(a, b);
    return *reinterpret_cast<unsigned*>(&t);
}
__device__ __forceinline__ float gelu_tanh(float v) {
    const float c0 = 0.7978845608028654f, c1 = 0.044715f;
    float u = c0 * (v + c1 * v * v * v);
    return 0.5f * v * (1.0f + tanhf(u));
}

// ---------------- K0 + router -------------------------------------------------
__global__ void k_init() { if (threadIdx.x < NEXP) g_count[threadIdx.x] = 0; }

__global__ __launch_bounds__(256) void k_router(const float* __restrict__ x,
                                                const float* __restrict__ rw,
                                                const float* __restrict__ rb) {
    const int row = blockIdx.x, tid = threadIdx.x;
    float l[NEXP];
#pragma unroll
    for (int e = 0; e < NEXP; ++e) l[e] = 0.f;
    const float* xr = x + (size_t)row * HDIM;
    for (int h = tid; h < HDIM; h += 256) {
        float xv = xr[h];
        float4 w0 = *(const float4*)(rw + (size_t)h * NEXP);
        float4 w1 = *(const float4*)(rw + (size_t)h * NEXP + 4);
        l[0] += xv * w0.x; l[1] += xv * w0.y; l[2] += xv * w0.z; l[3] += xv * w0.w;
        l[4] += xv * w1.x; l[5] += xv * w1.y; l[6] += xv * w1.z; l[7] += xv * w1.w;
    }
    __shared__ float red[NEXP][256];
#pragma unroll
    for (int e = 0; e < NEXP; ++e) red[e][tid] = l[e];
    __syncthreads();
    for (int s = 128; s > 0; s >>= 1) {
        if (tid < s) {
#pragma unroll
            for (int e = 0; e < NEXP; ++e) red[e][tid] += red[e][tid + s];
        }
        __syncthreads();
    }
    if (tid == 0) {
        float lg[NEXP];
#pragma unroll
        for (int e = 0; e < NEXP; ++e) lg[e] = red[e][0] + rb[e];
        int i0 = 0; float b0 = lg[0];
#pragma unroll
        for (int e = 1; e < NEXP; ++e) if (lg[e] > b0) { b0 = lg[e]; i0 = e; }
        int i1 = (i0 == 0) ? 1 : 0; float b1 = lg[i1];
#pragma unroll
        for (int e = 0; e < NEXP; ++e) if (e != i0 && lg[e] > b1) { b1 = lg[e]; i1 = e; }
        float ex = expf(b1 - b0);
        float g0 = 1.0f / (1.0f + ex);
        float g1 = ex * g0;
        int p0 = atomicAdd(&g_count[i0], 1);
        g_list[i0 * NTOK + p0] = row; g_lgate[i0 * NTOK + p0] = g0; g_lslot[i0 * NTOK + p0] = row * 2;
        int p1 = atomicAdd(&g_count[i1], 1);
        g_list[i1 * NTOK + p1] = row; g_lgate[i1 * NTOK + p1] = g1; g_lslot[i1 * NTOK + p1] = row * 2 + 1;
    }
}

// ---------------- prep: fp32 -> split bf16 ------------------------------------
__global__ __launch_bounds__(256) void k_cvt_x(const float* __restrict__ x) {
    size_t j = ((size_t)blockIdx.x * 256 + threadIdx.x) << 2;
    float4 v = *(const float4*)(x + j);
    float hx = __bfloat162float(__float2bfloat16(v.x));
    float hy = __bfloat162float(__float2bfloat16(v.y));
    float hz = __bfloat162float(__float2bfloat16(v.z));
    float hw = __bfloat162float(__float2bfloat16(v.w));
    uint2 ph = { pkbf2(hx, hy), pkbf2(hz, hw) };
    uint2 pl = { pkbf2(v.x - hx, v.y - hy), pkbf2(v.z - hz, v.w - hw) };
    *(uint2*)(g_xhi + j) = ph;
    *(uint2*)(g_xlo + j) = pl;
}

// transpose src[R][C] -> dst[C][R] (per z slice), split bf16, fully coalesced.
// DEVICE body: dh/dl are device-global pointers resolved in DEVICE code.
// (Passing __device__ globals as kernel args from host silently yields the
// host shadow address — that was the R8/R10 zero-output bug.)
__device__ __forceinline__ void cvt_w_body(const float* __restrict__ src,
                                           __nv_bfloat16* __restrict__ dh,
                                           __nv_bfloat16* __restrict__ dl,
                                           int R, int C) {
    __shared__ float t[64][33];
    const size_t zo = (size_t)blockIdx.z * R * C;
    src += zo; dh += zo; dl += zo;
    const int c0 = blockIdx.x * 32, r0 = blockIdx.y * 64;
    const int tid = threadIdx.x;
#pragma unroll
    for (int i = 0; i < 8; ++i) {
        int row = i * 8 + (tid >> 5);
        int col = tid & 31;
        t[row][col] = src[(size_t)(r0 + row) * C + c0 + col];
    }
    __syncthreads();
    const int drow = tid >> 3;            // 0..31 (column of src = row of dst)
    const int hc0  = (tid & 7) * 8;       // 0..56
    __align__(16) __nv_bfloat16 vh[8];
    __align__(16) __nv_bfloat16 vl[8];
#pragma unroll
    for (int i = 0; i < 8; ++i) {
        float v = t[hc0 + i][drow];
        float h = __bfloat162float(__float2bfloat16(v));
        vh[i] = __float2bfloat16(v);
        vl[i] = __float2bfloat16(v - h);
    }
    size_t o = (size_t)(c0 + drow) * R + r0 + hc0;
    *(uint4*)(dh + o) = *(uint4*)vh;
    *(uint4*)(dl + o) = *(uint4*)vl;
}

// grid = (DDIM/32, HDIM/64, NEXP): ew[e][h][d] -> g_ew{hi,lo}[e][d][h]
__global__ __launch_bounds__(256) void k_cvt_ew(const float* __restrict__ ew) {
    cvt_w_body(ew, g_ewhi, g_ewlo, HDIM, DDIM);
}
// grid = (DDIM/32, DDIM/64, 1): ow[d][f] -> g_ow{hi,lo}[f][d]
__global__ __launch_bounds__(256) void k_cvt_ow(const float* __restrict__ ow) {
    cvt_w_body(ow, g_owhi, g_owlo, DDIM, DDIM);
}

__global__ __launch_bounds__(256) void k_combine() {
    size_t j = ((size_t)blockIdx.x * 256 + threadIdx.x) << 2;
    size_t t = j >> 11, d = j & 2047;
    const float* s = g_scratch + (t << 12) + d;
    float4 a = *(const float4*)s;
    float4 b = *(const float4*)(s + DDIM);
    float cx = a.x + b.x, cy = a.y + b.y, cz = a.z + b.z, cw = a.w + b.w;
    float hx = __bfloat162float(__float2bfloat16(cx));
    float hy = __bfloat162float(__float2bfloat16(cy));
    float hz = __bfloat162float(__float2bfloat16(cz));
    float hw = __bfloat162float(__float2bfloat16(cw));
    uint2 ph = { pkbf2(hx, hy), pkbf2(hz, hw) };
    uint2 pl = { pkbf2(cx - hx, cy - hy), pkbf2(cz - hz, cw - hw) };
    *(uint2*)(g_chi + j) = ph;
    *(uint2*)(g_clo + j) = pl;
}

// ---------------- core GEMM mainloop (register-prefetch double buffer) --------
// 128x128 CTA tile, 256 thr = 8 warps (2x4), warp tile 64x32, BK=32 stages.
// Stage k: LDG stage k+1 into regs (no dep) -> HMMA stage k (~1500cyc hides
// the ~600cyc gmem latency) -> STS regs into the other buffer -> bar.
// 3-pass split-bf16: acc += Ahi*Bhi + Ahi*Blo + Alo*Bhi (fp32 accum in regs).

struct Frag { uint32_t a[4]; };

__device__ __forceinline__ void gemm_mainloop(
    char* smem, int tid,
    const __nv_bfloat16* Ahi, const __nv_bfloat16* Alo, size_t aStride, const int* arow,
    const __nv_bfloat16* Bhi, const __nv_bfloat16* Blo, size_t bRow0,
    float acc[4][4][4])
{
    const int lane = tid & 31, wid = tid >> 5;
    const int wm = (wid >> 2) * 64, wn = (wid & 3) * 32;
    const int g = lane >> 2, t = lane & 3;

    // fixed per-thread load geometry: rows (tid>>2) and 64+(tid>>2), seg tid&3
    const int lrow0 = tid >> 2, lseg = tid & 3;
    const int lrow1 = lrow0 + 64;
    const uint32_t so0 = (uint32_t)(lrow0 * ROWB + lseg * 16);
    const uint32_t so1 = (uint32_t)(lrow1 * ROWB + lseg * 16);
    const size_t ar0 = arow ? (size_t)arow[lrow0] : (size_t)lrow0;
    const size_t ar1 = arow ? (size_t)arow[lrow1] : (size_t)lrow1;
    const size_t aoff0 = ar0 * aStride + lseg * 8;
    const size_t aoff1 = ar1 * aStride + lseg * 8;
    const size_t boff0 = (bRow0 + lrow0) * aStride + lseg * 8;
    const size_t boff1 = (bRow0 + lrow1) * aStride + lseg * 8;

    uint4 pf[8];
    auto ldg_stage = [&](int kc) {
        const int kb = kc * BK;
        pf[0] = *(const uint4*)(Ahi + aoff0 + kb);
        pf[1] = *(const uint4*)(Alo + aoff0 + kb);
        pf[2] = *(const uint4*)(Bhi + boff0 + kb);
        pf[3] = *(const uint4*)(Blo + boff0 + kb);
        pf[4] = *(const uint4*)(Ahi + aoff1 + kb);
        pf[5] = *(const uint4*)(Alo + aoff1 + kb);
        pf[6] = *(const uint4*)(Bhi + boff1 + kb);
        pf[7] = *(const uint4*)(Blo + boff1 + kb);
    };
    auto sts_stage = [&](int bsel) {
        char* base = smem + SMEM_HDR + bsel * STAGE_BYTES;
        *(uint4*)(base + so0)                 = pf[0];
        *(uint4*)(base + TEN_BYTES + so0)     = pf[1];
        *(uint4*)(base + 2 * TEN_BYTES + so0) = pf[2];
        *(uint4*)(base + 3 * TEN_BYTES + so0) = pf[3];
        *(uint4*)(base + so1)                 = pf[4];
        *(uint4*)(base + TEN_BYTES + so1)     = pf[5];
        *(uint4*)(base + 2 * TEN_BYTES + so1) = pf[6];
        *(uint4*)(base + 3 * TEN_BYTES + so1) = pf[7];
    };

    ldg_stage(0);
    sts_stage(0);
    __syncthreads();

    for (int kc = 0; kc < NST; ++kc) {
        const int cur = kc & 1;
        const bool more = (kc + 1 < NST);
        if (more) ldg_stage(kc + 1);          // LDGs in flight, no consumer yet

        char* st = smem + SMEM_HDR + cur * STAGE_BYTES;
        char* pAh = st + (wm + g) * ROWB + t * 4;
        char* pAl = pAh + TEN_BYTES;
        char* pBh = st + 2 * TEN_BYTES + (wn + g) * ROWB + t * 4;
        char* pBl = pBh + TEN_BYTES;

#pragma unroll
        for (int ks = 0; ks < 2; ++ks) {
            const int ko = ks * 32;   // 16 bf16 = 32 bytes
            Frag Ah[4], Al[4];
            uint32_t Bh[4][2], Bl[4][2];
#pragma unroll
            for (int mt = 0; mt < 4; ++mt) {
                char* p = pAh + mt * (16 * ROWB) + ko;
                Ah[mt].a[0] = *(const uint32_t*)(p);
                Ah[mt].a[1] = *(const uint32_t*)(p + 8 * ROWB);
                Ah[mt].a[2] = *(const uint32_t*)(p + 16);
                Ah[mt].a[3] = *(const uint32_t*)(p + 8 * ROWB + 16);
            }
#pragma unroll
            for (int nt = 0; nt < 4; ++nt) {
                char* p = pBh + nt * (8 * ROWB) + ko;
                Bh[nt][0] = *(const uint32_t*)(p);
                Bh[nt][1] = *(const uint32_t*)(p + 16);
            }
#pragma unroll
            for (int mt = 0; mt < 4; ++mt)
#pragma unroll
                for (int nt = 0; nt < 4; ++nt)
                    mma16816(acc[mt][nt], Ah[mt].a, Bh[nt]);
#pragma unroll
            for (int nt = 0; nt < 4; ++nt) {
                char* p = pBl + nt * (8 * ROWB) + ko;
                Bl[nt][0] = *(const uint32_t*)(p);
                Bl[nt][1] = *(const uint32_t*)(p + 16);
            }
#pragma unroll
            for (int mt = 0; mt < 4; ++mt)
#pragma unroll
                for (int nt = 0; nt < 4; ++nt)
                    mma16816(acc[mt][nt], Ah[mt].a, Bl[nt]);
#pragma unroll
            for (int mt = 0; mt < 4; ++mt) {
                char* p = pAl + mt * (16 * ROWB) + ko;
                Al[mt].a[0] = *(const uint32_t*)(p);
                Al[mt].a[1] = *(const uint32_t*)(p + 8 * ROWB);
                Al[mt].a[2] = *(const uint32_t*)(p + 16);
                Al[mt].a[3] = *(const uint32_t*)(p + 8 * ROWB + 16);
            }
#pragma unroll
            for (int mt = 0; mt < 4; ++mt)
#pragma unroll
                for (int nt = 0; nt < 4; ++nt)
                    mma16816(acc[mt][nt], Al[mt].a, Bh[nt]);
        }

        if (more) sts_stage(cur ^ 1);         // writes the buffer NOT read this stage
        __syncthreads();
    }
}

// ---------------- K2: expert GEMM ---------------------------------------------
__global__ __launch_bounds__(256, 1) void k_expert_mma(const float* __restrict__ eb) {
    extern __shared__ char smem[];
    const int e = blockIdx.z;
    const int n = g_count[e];
    const int mbase = blockIdx.y * 128;
    if (mbase >= n) return;
    const int dbase = blockIdx.x * 128;
    const int tid = threadIdx.x, lane = tid & 31, wid = tid >> 5;

    int*   s_tok  = (int*)  (smem);
    float* s_gate = (float*)(smem + 512);
    int*   s_slot = (int*)  (smem + 1024);
    if (tid < 128) {
        int lr = mbase + tid;
        int safe = (lr < n) ? lr : mbase;
        s_tok [tid] = g_list [e * NTOK + safe];
        s_gate[tid] = g_lgate[e * NTOK + safe];
        s_slot[tid] = g_lslot[e * NTOK + safe];
    }
    __syncthreads();

    float acc[4][4][4];
#pragma unroll
    for (int mt = 0; mt < 4; ++mt)
#pragma unroll
        for (int nt = 0; nt < 4; ++nt)
#pragma unroll
            for (int i = 0; i < 4; ++i) acc[mt][nt][i] = 0.f;

    const size_t eoff = (size_t)e * DDIM * HDIM;
    gemm_mainloop(smem, tid,
                  g_xhi, g_xlo, HDIM, s_tok,
                  g_ewhi + eoff, g_ewlo + eoff, (size_t)dbase,
                  acc);

    const int wm = (wid >> 2) * 64, wn = (wid & 3) * 32;
    const int g = lane >> 2, t = lane & 3;
#pragma unroll
    for (int mt = 0; mt < 4; ++mt) {
#pragma unroll
        for (int half = 0; half < 2; ++half) {
            int rloc = wm + mt * 16 + g + half * 8;
            if (mbase + rloc < n) {
                float gate = s_gate[rloc];
                int   slot = s_slot[rloc];
                float* orow = g_scratch + (size_t)slot * DDIM + dbase;
                const float* brow = eb + (size_t)e * DDIM + dbase;
#pragma unroll
                for (int nt = 0; nt < 4; ++nt) {
                    int col = wn + nt * 8 + t * 2;
                    float v0 = acc[mt][nt][half * 2 + 0] + brow[col];
                    float v1 = acc[mt][nt][half * 2 + 1] + brow[col + 1];
                    float2 o = { gate * gelu_tanh(v0), gate * gelu_tanh(v1) };
                    *(float2*)(orow + col) = o;
                }
            }
        }
    }
}

// ---------------- K3: output projection ---------------------------------------
__global__ __launch_bounds__(256, 1) void k_outproj_mma(const float* __restrict__ ob,
                                                        float* __restrict__ out) {
    extern __shared__ char smem[];
    const int mbase = blockIdx.y * 128;
    const int dbase = blockIdx.x * 128;
    const int tid = threadIdx.x, lane = tid & 31, wid = tid >> 5;

    float acc[4][4][4];
#pragma unroll
    for (int mt = 0; mt < 4; ++mt)
#pragma unroll
        for (int nt = 0; nt < 4; ++nt)
#pragma unroll
            for (int i = 0; i < 4; ++i) acc[mt][nt][i] = 0.f;

    gemm_mainloop(smem, tid,
                  g_chi + (size_t)mbase * DDIM, g_clo + (size_t)mbase * DDIM, DDIM, nullptr,
                  g_owhi, g_owlo, (size_t)dbase,
                  acc);

    const int wm = (wid >> 2) * 64, wn = (wid & 3) * 32;
    const int g = lane >> 2, t = lane & 3;
#pragma unroll
    for (int mt = 0; mt < 4; ++mt) {
#pragma unroll
        for (int half = 0; half < 2; ++half) {
            int row = mbase + wm + mt * 16 + g + half * 8;
            float* orow = out + (size_t)row * DDIM + dbase;
            const float* brow = ob + dbase;
#pragma unroll
            for (int nt = 0; nt < 4; ++nt) {
                int col = wn + nt * 8 + t * 2;
                float2 o = { acc[mt][nt][half * 2 + 0] + brow[col],
                             acc[mt][nt][half * 2 + 1] + brow[col + 1] };
                *(float2*)(orow + col) = o;
            }
        }
    }
}

// ---------------- launch --------------------------------------------------------
extern "C" void kernel_launch(void* const* d_in, const int* in_sizes, int n_in,
                              void* d_out, int out_size) {
    const float* x  = (const float*)d_in[0];
    const float* rw = (const float*)d_in[1];
    const float* rb = (const float*)d_in[2];
    const float* ew = (const float*)d_in[3];
    const float* eb = (const float*)d_in[4];
    const float* ow = (const float*)d_in[5];
    const float* ob = (const float*)d_in[6];
    float* out = (float*)d_out;

    cudaFuncSetAttribute(k_expert_mma,  cudaFuncAttributeMaxDynamicSharedMemorySize, SMEM_GEMM);
    cudaFuncSetAttribute(k_outproj_mma, cudaFuncAttributeMaxDynamicSharedMemorySize, SMEM_GEMM);

    k_init<<<1, 32>>>();
    k_router<<<NTOK, 256>>>(x, rw, rb);
    k_cvt_x<<<(NTOK * HDIM / 4) / 256, 256>>>(x);
    k_cvt_ew<<<dim3(DDIM / 32, HDIM / 64, NEXP), 256>>>(ew);
    k_cvt_ow<<<dim3(DDIM / 32, DDIM / 64, 1),   256>>>(ow);

    dim3 ge(DDIM / 128, NTOK / 128, NEXP);
    k_expert_mma<<<ge, 256, SMEM_GEMM>>>(eb);

    k_combine<<<(NTOK * DDIM / 4) / 256, 256>>>();

    dim3 go(DDIM / 128, NTOK / 128);
    k_outproj_mma<<<go, 256, SMEM_GEMM>>>(ob, out);
}

// round 12
// speedup vs baseline: 4.7963x; 2.2190x over previous
#include <cuda_runtime.h>
#include <cuda_fp16.h>
#include <math.h>
#include <stdint.h>

#define NTOK 4096   // B*S
#define HDIM 2048
#define DDIM 2048
#define NEXP 8
#define BK   32                 // fp16 K elements per stage
#define NST  (HDIM / BK)        // 64 stages (HDIM == DDIM)

// padded smem rows: 32 fp16 data (64 B) + 16 B pad = 80 B -> conflict-free frags
#define ROWB 80
#define TEN_BYTES (128 * ROWB)          // 10240 B per tensor tile
#define STAGE_BYTES (2 * TEN_BYTES)     // A | B = 20480
#define SMEM_HDR 1536
#define SMEM_GEMM (SMEM_HDR + 2 * STAGE_BYTES)   // 42496 B -> 2 CTAs/SM

// ---------------- scratch (device globals; no allocations allowed) ----------
__device__ int   g_count[NEXP];
__device__ int   g_list [NEXP * NTOK];
__device__ float g_lgate[NEXP * NTOK];
__device__ int   g_lslot[NEXP * NTOK];
__device__ __align__(16) __half g_scr[(size_t)2 * NTOK * DDIM];            // fp16 expert outputs
__device__ __align__(16) __half g_xh [(size_t)NTOK * HDIM];
__device__ __align__(16) __half g_ewh[(size_t)NEXP * DDIM * HDIM];         // [e][d][h]
__device__ __align__(16) __half g_owh[(size_t)DDIM * DDIM];                // [f][d]
__device__ __align__(16) __half g_ch [(size_t)NTOK * DDIM];                // combined fp16

// ---------------- helpers ----------------------------------------------------
__device__ __forceinline__ void mma16816(float* c, const uint32_t* a, const uint32_t* b) {
    asm volatile(
        "mma.sync.aligned.m16n8k16.row.col.f32.f16.f16.f32 "
        "{%0,%1,%2,%3}, {%4,%5,%6,%7}, {%8,%9}, {%0,%1,%2,%3};"
        : "+f"(c[0]), "+f"(c[1]), "+f"(c[2]), "+f"(c[3])
        : "r"(a[0]), "r"(a[1]), "r"(a[2]), "r"(a[3]), "r"(b[0]), "r"(b[1]));
}
__device__ __forceinline__ unsigned pkh2(float a, float b) {
    __half2 t = __floats2half2_rn(a, b);
    return *reinterpret_cast<unsigned*>(&t);
}
__device__ __forceinline__ float gelu_tanh(float v) {
    const float c0 = 0.7978845608028654f, c1 = 0.044715f;
    float u = c0 * (v + c1 * v * v * v);
    return 0.5f * v * (1.0f + tanhf(u));
}

// ---------------- K0 + router (fp32, exact top-2) -----------------------------
__global__ void k_init() { if (threadIdx.x < NEXP) g_count[threadIdx.x] = 0; }

__global__ __launch_bounds__(256) void k_router(const float* __restrict__ x,
                                                const float* __restrict__ rw,
                                                const float* __restrict__ rb) {
    const int row = blockIdx.x, tid = threadIdx.x;
    float l[NEXP];
#pragma unroll
    for (int e = 0; e < NEXP; ++e) l[e] = 0.f;
    const float* xr = x + (size_t)row * HDIM;
    for (int h = tid; h < HDIM; h += 256) {
        float xv = xr[h];
        float4 w0 = *(const float4*)(rw + (size_t)h * NEXP);
        float4 w1 = *(const float4*)(rw + (size_t)h * NEXP + 4);
        l[0] += xv * w0.x; l[1] += xv * w0.y; l[2] += xv * w0.z; l[3] += xv * w0.w;
        l[4] += xv * w1.x; l[5] += xv * w1.y; l[6] += xv * w1.z; l[7] += xv * w1.w;
    }
    __shared__ float red[NEXP][256];
#pragma unroll
    for (int e = 0; e < NEXP; ++e) red[e][tid] = l[e];
    __syncthreads();
    for (int s = 128; s > 0; s >>= 1) {
        if (tid < s) {
#pragma unroll
            for (int e = 0; e < NEXP; ++e) red[e][tid] += red[e][tid + s];
        }
        __syncthreads();
    }
    if (tid == 0) {
        float lg[NEXP];
#pragma unroll
        for (int e = 0; e < NEXP; ++e) lg[e] = red[e][0] + rb[e];
        int i0 = 0; float b0 = lg[0];
#pragma unroll
        for (int e = 1; e < NEXP; ++e) if (lg[e] > b0) { b0 = lg[e]; i0 = e; }
        int i1 = (i0 == 0) ? 1 : 0; float b1 = lg[i1];
#pragma unroll
        for (int e = 0; e < NEXP; ++e) if (e != i0 && lg[e] > b1) { b1 = lg[e]; i1 = e; }
        float ex = expf(b1 - b0);
        float g0 = 1.0f / (1.0f + ex);
        float g1 = ex * g0;
        int p0 = atomicAdd(&g_count[i0], 1);
        g_list[i0 * NTOK + p0] = row; g_lgate[i0 * NTOK + p0] = g0; g_lslot[i0 * NTOK + p0] = row * 2;
        int p1 = atomicAdd(&g_count[i1], 1);
        g_list[i1 * NTOK + p1] = row; g_lgate[i1 * NTOK + p1] = g1; g_lslot[i1 * NTOK + p1] = row * 2 + 1;
    }
}

// ---------------- prep: fp32 -> fp16 ------------------------------------------
// 8 elements/thread, 16B stores. grid = NTOK*HDIM/8/256
__global__ __launch_bounds__(256) void k_cvt_x(const float* __restrict__ x) {
    size_t j = ((size_t)blockIdx.x * 256 + threadIdx.x) << 3;
    float4 a = *(const float4*)(x + j);
    float4 b = *(const float4*)(x + j + 4);
    uint4 o = { pkh2(a.x, a.y), pkh2(a.z, a.w), pkh2(b.x, b.y), pkh2(b.z, b.w) };
    *(uint4*)(g_xh + j) = o;
}

// transpose src[R][C] -> dst[C][R] (per z slice), fp16, fully coalesced.
// Globals referenced only inside __device__ code (host-shadow-pointer trap).
__device__ __forceinline__ void cvt_w_body(const float* __restrict__ src,
                                           __half* __restrict__ dst,
                                           int R, int C) {
    __shared__ float t[64][33];
    const size_t zo = (size_t)blockIdx.z * R * C;
    src += zo; dst += zo;
    const int c0 = blockIdx.x * 32, r0 = blockIdx.y * 64;
    const int tid = threadIdx.x;
#pragma unroll
    for (int i = 0; i < 8; ++i) {
        int row = i * 8 + (tid >> 5);
        int col = tid & 31;
        t[row][col] = src[(size_t)(r0 + row) * C + c0 + col];
    }
    __syncthreads();
    const int drow = tid >> 3;            // 0..31
    const int hc0  = (tid & 7) * 8;       // 0..56
    __align__(16) __half vh[8];
#pragma unroll
    for (int i = 0; i < 8; ++i)
        vh[i] = __float2half_rn(t[hc0 + i][drow]);
    size_t o = (size_t)(c0 + drow) * R + r0 + hc0;
    *(uint4*)(dst + o) = *(uint4*)vh;
}
// grid = (DDIM/32, HDIM/64, NEXP)
__global__ __launch_bounds__(256) void k_cvt_ew(const float* __restrict__ ew) {
    cvt_w_body(ew, g_ewh, HDIM, DDIM);
}
// grid = (DDIM/32, DDIM/64, 1)
__global__ __launch_bounds__(256) void k_cvt_ow(const float* __restrict__ ow) {
    cvt_w_body(ow, g_owh, DDIM, DDIM);
}

// combined = scr[2t] + scr[2t+1] (fp32 add), -> fp16. 8 elems/thread.
__global__ __launch_bounds__(256) void k_combine() {
    size_t j = ((size_t)blockIdx.x * 256 + threadIdx.x) << 3;
    size_t t = j >> 11, d = j & 2047;
    const __half* s0 = g_scr + (t << 12) + d;     // slot 2t
    const __half* s1 = s0 + DDIM;                 // slot 2t+1
    uint4 u0 = *(const uint4*)s0;
    uint4 u1 = *(const uint4*)s1;
    const __half2* h0 = (const __half2*)&u0;
    const __half2* h1 = (const __half2*)&u1;
    uint4 o;
    unsigned* op = (unsigned*)&o;
#pragma unroll
    for (int i = 0; i < 4; ++i) {
        float2 a = __half22float2(h0[i]);
        float2 b = __half22float2(h1[i]);
        op[i] = pkh2(a.x + b.x, a.y + b.y);
    }
    *(uint4*)(g_ch + j) = o;
}

// ---------------- core GEMM mainloop (single-pass fp16, reg-prefetch) ---------
// 128x128 CTA tile, 256 thr = 8 warps (2x4), warp tile 64x32, BK=32 stages.
// Stage k: LDG stage k+1 into regs -> 32 HMMA stage k -> STS other buffer -> bar.
// 2 CTAs/SM: the partner CTA's HMMAs fill this CTA's sync/load shadows.

struct Frag { uint32_t a[4]; };

__device__ __forceinline__ void gemm_mainloop(
    char* smem, int tid,
    const __half* A, size_t aStride, const int* arow,
    const __half* B, size_t bRow0,
    float acc[4][4][4])
{
    const int lane = tid & 31, wid = tid >> 5;
    const int wm = (wid >> 2) * 64, wn = (wid & 3) * 32;
    const int g = lane >> 2, t = lane & 3;

    const int lrow0 = tid >> 2, lseg = tid & 3;
    const int lrow1 = lrow0 + 64;
    const uint32_t so0 = (uint32_t)(lrow0 * ROWB + lseg * 16);
    const uint32_t so1 = (uint32_t)(lrow1 * ROWB + lseg * 16);
    const size_t ar0 = arow ? (size_t)arow[lrow0] : (size_t)lrow0;
    const size_t ar1 = arow ? (size_t)arow[lrow1] : (size_t)lrow1;
    const size_t aoff0 = ar0 * aStride + lseg * 8;
    const size_t aoff1 = ar1 * aStride + lseg * 8;
    const size_t boff0 = (bRow0 + lrow0) * aStride + lseg * 8;
    const size_t boff1 = (bRow0 + lrow1) * aStride + lseg * 8;

    uint4 pf[4];
    auto ldg_stage = [&](int kc) {
        const int kb = kc * BK;
        pf[0] = *(const uint4*)(A + aoff0 + kb);
        pf[1] = *(const uint4*)(B + boff0 + kb);
        pf[2] = *(const uint4*)(A + aoff1 + kb);
        pf[3] = *(const uint4*)(B + boff1 + kb);
    };
    auto sts_stage = [&](int bsel) {
        char* base = smem + SMEM_HDR + bsel * STAGE_BYTES;
        *(uint4*)(base + so0)             = pf[0];
        *(uint4*)(base + TEN_BYTES + so0) = pf[1];
        *(uint4*)(base + so1)             = pf[2];
        *(uint4*)(base + TEN_BYTES + so1) = pf[3];
    };

    ldg_stage(0);
    sts_stage(0);
    __syncthreads();

    for (int kc = 0; kc < NST; ++kc) {
        const int cur = kc & 1;
        const bool more = (kc + 1 < NST);
        if (more) ldg_stage(kc + 1);          // in flight; consumed only at sts

        char* st = smem + SMEM_HDR + cur * STAGE_BYTES;
        char* pA = st + (wm + g) * ROWB + t * 4;
        char* pB = st + TEN_BYTES + (wn + g) * ROWB + t * 4;

#pragma unroll
        for (int ks = 0; ks < 2; ++ks) {
            const int ko = ks * 32;   // 16 fp16 = 32 bytes
            Frag Ah[4];
            uint32_t Bh[4][2];
#pragma unroll
            for (int mt = 0; mt < 4; ++mt) {
                char* p = pA + mt * (16 * ROWB) + ko;
                Ah[mt].a[0] = *(const uint32_t*)(p);
                Ah[mt].a[1] = *(const uint32_t*)(p + 8 * ROWB);
                Ah[mt].a[2] = *(const uint32_t*)(p + 16);
                Ah[mt].a[3] = *(const uint32_t*)(p + 8 * ROWB + 16);
            }
#pragma unroll
            for (int nt = 0; nt < 4; ++nt) {
                char* p = pB + nt * (8 * ROWB) + ko;
                Bh[nt][0] = *(const uint32_t*)(p);
                Bh[nt][1] = *(const uint32_t*)(p + 16);
            }
#pragma unroll
            for (int mt = 0; mt < 4; ++mt)
#pragma unroll
                for (int nt = 0; nt < 4; ++nt)
                    mma16816(acc[mt][nt], Ah[mt].a, Bh[nt]);
        }

        if (more) sts_stage(cur ^ 1);
        __syncthreads();
    }
}

// ---------------- K2: expert GEMM ---------------------------------------------
__global__ __launch_bounds__(256, 2) void k_expert_mma(const float* __restrict__ eb) {
    extern __shared__ char smem[];
    const int e = blockIdx.z;
    const int n = g_count[e];
    const int mbase = blockIdx.y * 128;
    if (mbase >= n) return;
    const int dbase = blockIdx.x * 128;
    const int tid = threadIdx.x, lane = tid & 31, wid = tid >> 5;

    int*   s_tok  = (int*)  (smem);
    float* s_gate = (float*)(smem + 512);
    int*   s_slot = (int*)  (smem + 1024);
    if (tid < 128) {
        int lr = mbase + tid;
        int safe = (lr < n) ? lr : mbase;
        s_tok [tid] = g_list [e * NTOK + safe];
        s_gate[tid] = g_lgate[e * NTOK + safe];
        s_slot[tid] = g_lslot[e * NTOK + safe];
    }
    __syncthreads();

    float acc[4][4][4];
#pragma unroll
    for (int mt = 0; mt < 4; ++mt)
#pragma unroll
        for (int nt = 0; nt < 4; ++nt)
#pragma unroll
            for (int i = 0; i < 4; ++i) acc[mt][nt][i] = 0.f;

    gemm_mainloop(smem, tid,
                  g_xh, HDIM, s_tok,
                  g_ewh + (size_t)e * DDIM * HDIM, (size_t)dbase,
                  acc);

    // epilogue: gate * gelu(acc + bias) -> fp16 scratch[slot]
    const int wm = (wid >> 2) * 64, wn = (wid & 3) * 32;
    const int g = lane >> 2, t = lane & 3;
#pragma unroll
    for (int mt = 0; mt < 4; ++mt) {
#pragma unroll
        for (int half_ = 0; half_ < 2; ++half_) {
            int rloc = wm + mt * 16 + g + half_ * 8;
            if (mbase + rloc < n) {
                float gate = s_gate[rloc];
                int   slot = s_slot[rloc];
                __half* orow = g_scr + (size_t)slot * DDIM + dbase;
                const float* brow = eb + (size_t)e * DDIM + dbase;
#pragma unroll
                for (int nt = 0; nt < 4; ++nt) {
                    int col = wn + nt * 8 + t * 2;
                    float v0 = gate * gelu_tanh(acc[mt][nt][half_ * 2 + 0] + brow[col]);
                    float v1 = gate * gelu_tanh(acc[mt][nt][half_ * 2 + 1] + brow[col + 1]);
                    *(unsigned*)(orow + col) = pkh2(v0, v1);
                }
            }
        }
    }
}

// ---------------- K3: output projection ---------------------------------------
__global__ __launch_bounds__(256, 2) void k_outproj_mma(const float* __restrict__ ob,
                                                        float* __restrict__ out) {
    extern __shared__ char smem[];
    const int mbase = blockIdx.y * 128;
    const int dbase = blockIdx.x * 128;
    const int tid = threadIdx.x, lane = tid & 31, wid = tid >> 5;

    float acc[4][4][4];
#pragma unroll
    for (int mt = 0; mt < 4; ++mt)
#pragma unroll
        for (int nt = 0; nt < 4; ++nt)
#pragma unroll
            for (int i = 0; i < 4; ++i) acc[mt][nt][i] = 0.f;

    gemm_mainloop(smem, tid,
                  g_ch + (size_t)mbase * DDIM, DDIM, nullptr,
                  g_owh, (size_t)dbase,
                  acc);

    const int wm = (wid >> 2) * 64, wn = (wid & 3) * 32;
    const int g = lane >> 2, t = lane & 3;
#pragma unroll
    for (int mt = 0; mt < 4; ++mt) {
#pragma unroll
        for (int half_ = 0; half_ < 2; ++half_) {
            int row = mbase + wm + mt * 16 + g + half_ * 8;
            float* orow = out + (size_t)row * DDIM + dbase;
            const float* brow = ob + dbase;
#pragma unroll
            for (int nt = 0; nt < 4; ++nt) {
                int col = wn + nt * 8 + t * 2;
                float2 o = { acc[mt][nt][half_ * 2 + 0] + brow[col],
                             acc[mt][nt][half_ * 2 + 1] + brow[col + 1] };
                *(float2*)(orow + col) = o;
            }
        }
    }
}

// ---------------- launch --------------------------------------------------------
extern "C" void kernel_launch(void* const* d_in, const int* in_sizes, int n_in,
                              void* d_out, int out_size) {
    const float* x  = (const float*)d_in[0];
    const float* rw = (const float*)d_in[1];
    const float* rb = (const float*)d_in[2];
    const float* ew = (const float*)d_in[3];
    const float* eb = (const float*)d_in[4];
    const float* ow = (const float*)d_in[5];
    const float* ob = (const float*)d_in[6];
    float* out = (float*)d_out;

    k_init<<<1, 32>>>();
    k_router<<<NTOK, 256>>>(x, rw, rb);
    k_cvt_x<<<(NTOK * HDIM / 8) / 256, 256>>>(x);
    k_cvt_ew<<<dim3(DDIM / 32, HDIM / 64, NEXP), 256>>>(ew);
    k_cvt_ow<<<dim3(DDIM / 32, DDIM / 64, 1),   256>>>(ow);

    dim3 ge(DDIM / 128, NTOK / 128, NEXP);
    k_expert_mma<<<ge, 256, SMEM_GEMM>>>(eb);

    k_combine<<<(NTOK * DDIM / 8) / 256, 256>>>();

    dim3 go(DDIM / 128, NTOK / 128);
    k_outproj_mma<<<go, 256, SMEM_GEMM>>>(ob, out);
}